// round 13
// baseline (speedup 1.0000x reference)
#include <cuda_runtime.h>
#include <cuda_fp16.h>
#include <cstdint>

// ---------------------------------------------------------------------------
// SimpleGCN on B200, round 13: R12 (283us) + pipelined gather.
//   - CSR rows padded to even edge count -> 16B-aligned int4 record loads
//     (2 edges per LDG, halves record issue)
//   - software pipeline: next group's records prefetched while current
//     group's 4 h-row loads are in flight (record->h latency paid once)
//   - everything else identical to R12 (fp16 h, 16 lanes/node, ffma2 gemm)
// ---------------------------------------------------------------------------

#define MAXN (1 << 17)
#define MAXE (1 << 21)
#define FDIM 64

__device__ __half g_h[(size_t)MAXN * FDIM];      // fp16 transformed features
__device__ float  g_acc[(size_t)MAXN * FDIM];    // fp32 layer outputs
__device__ float  g_dinv[MAXN];
__device__ int    g_cnt[MAXN];
__device__ int    g_row[MAXN];
__device__ int    g_cur[MAXN];
__device__ int    g_total;
__device__ int2   g_edata[MAXE];
__device__ int    g_is64;

// --- packed f32x2 helpers ---
__device__ __forceinline__ unsigned long long ffma2(
    unsigned long long a, unsigned long long b, unsigned long long c) {
    unsigned long long d;
    asm("fma.rn.f32x2 %0, %1, %2, %3;" : "=l"(d) : "l"(a), "l"(b), "l"(c));
    return d;
}
__device__ __forceinline__ unsigned long long pack2(float x) {
    unsigned long long p;
    asm("mov.b64 %0, {%1, %1};" : "=l"(p) : "f"(x));
    return p;
}
__device__ __forceinline__ float2 unpack2(unsigned long long p) {
    float lo, hi;
    asm("mov.b64 {%0, %1}, %2;" : "=f"(lo), "=f"(hi) : "l"(p));
    return make_float2(lo, hi);
}
__device__ __forceinline__ uint32_t h2_as_u32(__half2 v) {
    return *reinterpret_cast<uint32_t*>(&v);
}

// --- launch 0: dtype detect + zero counters
__global__ void k_prep0(const unsigned int* __restrict__ w, long long nwords, int n) {
    int i = blockIdx.x * blockDim.x + threadIdx.x;
    if (i < n) { g_cnt[i] = 0; g_cur[i] = 0; }
    if (i == 0) g_total = 0;
    if (blockIdx.x == 0) {
        __shared__ int cnt;
        if (threadIdx.x == 0) cnt = 0;
        __syncthreads();
        int zeros = 0;
        for (long long j = threadIdx.x; j < 2048 && j < nwords; j += blockDim.x)
            if ((j & 1) && w[j] == 0u) zeros++;
        atomicAdd(&cnt, zeros);
        __syncthreads();
        if (threadIdx.x == 0) g_is64 = (cnt > 512) ? 1 : 0;
    }
}

__device__ __forceinline__ int load_idx(const void* e, long long pos) {
    if (g_is64) return (int)((const long long*)e)[pos];
    return ((const int*)e)[pos];
}

// --- launch 1: in-degree histogram
__global__ void k_deg(const void* __restrict__ e, long long E) {
    long long i = (long long)blockIdx.x * blockDim.x + threadIdx.x;
    if (i >= E) return;
    atomicAdd(&g_cnt[load_idx(e, E + i)], 1);
}

// --- launch 2: dinv + disjoint range allocation, PADDED TO EVEN edge count
//     (=> every row start is 16B-aligned in int2 units; pad slot unused)
__global__ void k_dinv_alloc(int n) {
    int i = blockIdx.x * blockDim.x + threadIdx.x;
    if (i >= n) return;
    int c = g_cnt[i];
    g_dinv[i] = rsqrtf((float)(1 + c));   // +1 self loop
    g_row[i] = atomicAdd(&g_total, (c + 1) & ~1);
}

// --- launch 3: CSR fill {src, norm}   <- profiled slot (canary: ~35.5us)
__global__ void k_fill(const void* __restrict__ e, long long E) {
    long long i = (long long)blockIdx.x * blockDim.x + threadIdx.x;
    if (i >= E) return;
    int s, d;
    if (g_is64) {
        const long long* p = (const long long*)e;
        s = (int)p[i]; d = (int)p[E + i];
    } else {
        const int* p = (const int*)e;
        s = p[i]; d = p[E + i];
    }
    int pos = g_row[d] + atomicAdd(&g_cur[d], 1);
    g_edata[pos] = make_int2(s, __float_as_int(g_dinv[s] * g_dinv[d]));
}

// --- GEMM: h = act(in) @ W via packed f32x2; fp16 epilogue
template <int LRELU>
__global__ void __launch_bounds__(128)
k_gemm(const float* __restrict__ in, const float* __restrict__ W,
       __half* __restrict__ h, int n) {
    __shared__ float Ws[FDIM * FDIM];
    for (int i = threadIdx.x; i < FDIM * FDIM; i += blockDim.x) Ws[i] = W[i];
    __syncthreads();

    int r = blockIdx.x * blockDim.x + threadIdx.x;
    if (r >= n) return;

    unsigned long long acc2[FDIM / 2];
#pragma unroll
    for (int j = 0; j < FDIM / 2; j++) acc2[j] = 0ull;

    const float4* x4 = (const float4*)(in + (size_t)r * FDIM);
#pragma unroll 4
    for (int k4 = 0; k4 < FDIM / 4; k4++) {
        float4 xv = __ldg(x4 + k4);
        float xs[4] = {xv.x, xv.y, xv.z, xv.w};
#pragma unroll
        for (int kk = 0; kk < 4; kk++) {
            float xk = xs[kk];
            if (LRELU) xk = xk > 0.0f ? xk : 0.01f * xk;
            unsigned long long xk2 = pack2(xk);
            const ulonglong2* Wr = (const ulonglong2*)&Ws[(k4 * 4 + kk) * FDIM];
#pragma unroll
            for (int j = 0; j < FDIM / 4; j++) {
                ulonglong2 w2 = Wr[j];
                acc2[2 * j]     = ffma2(xk2, w2.x, acc2[2 * j]);
                acc2[2 * j + 1] = ffma2(xk2, w2.y, acc2[2 * j + 1]);
            }
        }
    }

    uint4* hr = (uint4*)(h + (size_t)r * FDIM);
#pragma unroll
    for (int j = 0; j < 8; j++) {
        float2 p0 = unpack2(acc2[4 * j + 0]);
        float2 p1 = unpack2(acc2[4 * j + 1]);
        float2 p2 = unpack2(acc2[4 * j + 2]);
        float2 p3 = unpack2(acc2[4 * j + 3]);
        uint4 v;
        v.x = h2_as_u32(__floats2half2_rn(p0.x, p0.y));
        v.y = h2_as_u32(__floats2half2_rn(p1.x, p1.y));
        v.z = h2_as_u32(__floats2half2_rn(p2.x, p2.y));
        v.w = h2_as_u32(__floats2half2_rn(p3.x, p3.y));
        hr[j] = v;
    }
}

// --- CSR gather: 16 lanes/node, lane owns 4 cols (uint2 = 4 halves = 8B).
//     int4 record loads (2 edges each) + next-group prefetch pipeline.
__device__ __forceinline__ void acc_u2(uint2 u, float nn, float4& a) {
    __half2 h0 = *reinterpret_cast<__half2*>(&u.x);
    __half2 h1 = *reinterpret_cast<__half2*>(&u.y);
    float2 f0 = __half22float2(h0);
    float2 f1 = __half22float2(h1);
    a.x = fmaf(f0.x, nn, a.x); a.y = fmaf(f0.y, nn, a.y);
    a.z = fmaf(f1.x, nn, a.z); a.w = fmaf(f1.y, nn, a.w);
}

__global__ void __launch_bounds__(256)
k_gather(const __half* __restrict__ h, float* __restrict__ out,
         const float* __restrict__ b, int n) {
    int node = blockIdx.x * 16 + (threadIdx.x >> 4);
    if (node >= n) return;
    int l16 = threadIdx.x & 15;              // owns cols [4*l16, 4*l16+4)

    const uint2* h2 = (const uint2*)h;       // 16 uint2 per row
    int start = g_row[node];                 // even => 16B-aligned
    int deg   = g_cnt[node];
    float di  = g_dinv[node];
    float sn  = di * di;

    float4 a = __ldg((const float4*)b + l16);
    acc_u2(h2[(size_t)node * 16 + l16], sn, a);   // self loop

    const int2* ed  = g_edata + start;
    const int4* ed4 = (const int4*)ed;       // {s0,n0,s1,n1}
    int ngr = deg >> 2;                      // groups of 4 edges

    int4 ra, rb;
    if (ngr > 0) { ra = ed4[0]; rb = ed4[1]; }
    for (int g = 0; g < ngr; g++) {
        int4 rc = ra, rd = rb;
        if (g + 1 < ngr) { ra = ed4[2 * g + 2]; rb = ed4[2 * g + 3]; }
        uint2 v0 = h2[(size_t)rc.x * 16 + l16];
        uint2 v1 = h2[(size_t)rc.z * 16 + l16];
        uint2 v2 = h2[(size_t)rd.x * 16 + l16];
        uint2 v3 = h2[(size_t)rd.z * 16 + l16];
        acc_u2(v0, __int_as_float(rc.y), a);
        acc_u2(v1, __int_as_float(rc.w), a);
        acc_u2(v2, __int_as_float(rd.y), a);
        acc_u2(v3, __int_as_float(rd.w), a);
    }
    for (int e = ngr << 2; e < deg; e++) {
        int2 ee = ed[e];
        uint2 v = h2[(size_t)ee.x * 16 + l16];
        acc_u2(v, __int_as_float(ee.y), a);
    }

    ((float4*)out)[(size_t)node * 16 + l16] = a;
}

extern "C" void kernel_launch(void* const* d_in, const int* in_sizes, int n_in,
                              void* d_out, int out_size) {
    const float* x  = (const float*)d_in[0];
    const void*  ei = d_in[1];
    const float* W1 = (const float*)d_in[2];
    const float* b1 = (const float*)d_in[3];
    const float* W2 = (const float*)d_in[4];
    const float* b2 = (const float*)d_in[5];
    const float* W3 = (const float*)d_in[6];
    const float* b3 = (const float*)d_in[7];
    float* out = (float*)d_out;

    int n = in_sizes[0] / FDIM;
    long long E = (long long)in_sizes[1] / 2;

    __half* hbuf;
    float* accbuf;
    cudaGetSymbolAddress((void**)&hbuf, g_h);
    cudaGetSymbolAddress((void**)&accbuf, g_acc);

    int nb_n  = (n + 255) / 256;
    int nb_e  = (int)((E + 255) / 256);
    int nb_g  = (n + 127) / 128;
    int nb_ga = (n + 15) / 16;

    k_prep0<<<nb_n, 256>>>((const unsigned int*)ei, 2 * E, n);  // 0
    k_deg<<<nb_e, 256>>>(ei, E);                                // 1
    k_dinv_alloc<<<nb_n, 256>>>(n);                             // 2
    k_fill<<<nb_e, 256>>>(ei, E);                               // 3 <- profiled
    k_gemm<0><<<nb_g, 128>>>(x, W1, hbuf, n);                   // 4
    k_gather<<<nb_ga, 256>>>(hbuf, accbuf, b1, n);              // 5
    k_gemm<1><<<nb_g, 128>>>(accbuf, W2, hbuf, n);              // 6
    k_gather<<<nb_ga, 256>>>(hbuf, accbuf, b2, n);              // 7
    k_gemm<1><<<nb_g, 128>>>(accbuf, W3, hbuf, n);              // 8
    k_gather<<<nb_ga, 256>>>(hbuf, out, b3, n);                 // 9
}

// round 14
// speedup vs baseline: 1.0342x; 1.0342x over previous
#include <cuda_runtime.h>
#include <cuda_fp16.h>
#include <cstdint>

// ---------------------------------------------------------------------------
// SimpleGCN on B200, round 14: R12 (283us, best) + dual-chain gather.
//   Each node's edges split into two independent chains [0,m) and [m,2m)
//   walked in lockstep by the same thread -> 2x independent record->h
//   dependency chains, 4 loads in flight, branchless (R13's branchy
//   prefetch regressed: BSSY/BSYNC per iteration).
//   Everything else identical to R12: fp16 h, 16 lanes/node, ffma2 gemm,
//   scan-free CSR prep (fill canary ~35.5us at profiled slot 3).
// ---------------------------------------------------------------------------

#define MAXN (1 << 17)
#define MAXE (1 << 21)
#define FDIM 64

__device__ __half g_h[(size_t)MAXN * FDIM];      // fp16 transformed features
__device__ float  g_acc[(size_t)MAXN * FDIM];    // fp32 layer outputs
__device__ float  g_dinv[MAXN];
__device__ int    g_cnt[MAXN];
__device__ int    g_row[MAXN];
__device__ int    g_cur[MAXN];
__device__ int    g_total;
__device__ int2   g_edata[MAXE];
__device__ int    g_is64;

// --- packed f32x2 helpers ---
__device__ __forceinline__ unsigned long long ffma2(
    unsigned long long a, unsigned long long b, unsigned long long c) {
    unsigned long long d;
    asm("fma.rn.f32x2 %0, %1, %2, %3;" : "=l"(d) : "l"(a), "l"(b), "l"(c));
    return d;
}
__device__ __forceinline__ unsigned long long pack2(float x) {
    unsigned long long p;
    asm("mov.b64 %0, {%1, %1};" : "=l"(p) : "f"(x));
    return p;
}
__device__ __forceinline__ float2 unpack2(unsigned long long p) {
    float lo, hi;
    asm("mov.b64 {%0, %1}, %2;" : "=f"(lo), "=f"(hi) : "l"(p));
    return make_float2(lo, hi);
}
__device__ __forceinline__ uint32_t h2_as_u32(__half2 v) {
    return *reinterpret_cast<uint32_t*>(&v);
}

// --- launch 0: dtype detect + zero counters
__global__ void k_prep0(const unsigned int* __restrict__ w, long long nwords, int n) {
    int i = blockIdx.x * blockDim.x + threadIdx.x;
    if (i < n) { g_cnt[i] = 0; g_cur[i] = 0; }
    if (i == 0) g_total = 0;
    if (blockIdx.x == 0) {
        __shared__ int cnt;
        if (threadIdx.x == 0) cnt = 0;
        __syncthreads();
        int zeros = 0;
        for (long long j = threadIdx.x; j < 2048 && j < nwords; j += blockDim.x)
            if ((j & 1) && w[j] == 0u) zeros++;
        atomicAdd(&cnt, zeros);
        __syncthreads();
        if (threadIdx.x == 0) g_is64 = (cnt > 512) ? 1 : 0;
    }
}

__device__ __forceinline__ int load_idx(const void* e, long long pos) {
    if (g_is64) return (int)((const long long*)e)[pos];
    return ((const int*)e)[pos];
}

// --- launch 1: in-degree histogram
__global__ void k_deg(const void* __restrict__ e, long long E) {
    long long i = (long long)blockIdx.x * blockDim.x + threadIdx.x;
    if (i >= E) return;
    atomicAdd(&g_cnt[load_idx(e, E + i)], 1);
}

// --- launch 2: dinv + unordered disjoint CSR range allocation
__global__ void k_dinv_alloc(int n) {
    int i = blockIdx.x * blockDim.x + threadIdx.x;
    if (i >= n) return;
    int c = g_cnt[i];
    g_dinv[i] = rsqrtf((float)(1 + c));   // +1 self loop
    g_row[i] = atomicAdd(&g_total, c);
}

// --- launch 3: CSR fill {src, norm}   <- profiled slot (canary: ~35.5us)
__global__ void k_fill(const void* __restrict__ e, long long E) {
    long long i = (long long)blockIdx.x * blockDim.x + threadIdx.x;
    if (i >= E) return;
    int s, d;
    if (g_is64) {
        const long long* p = (const long long*)e;
        s = (int)p[i]; d = (int)p[E + i];
    } else {
        const int* p = (const int*)e;
        s = p[i]; d = p[E + i];
    }
    int pos = g_row[d] + atomicAdd(&g_cur[d], 1);
    g_edata[pos] = make_int2(s, __float_as_int(g_dinv[s] * g_dinv[d]));
}

// --- GEMM: h = act(in) @ W via packed f32x2; fp16 epilogue
template <int LRELU>
__global__ void __launch_bounds__(128)
k_gemm(const float* __restrict__ in, const float* __restrict__ W,
       __half* __restrict__ h, int n) {
    __shared__ float Ws[FDIM * FDIM];
    for (int i = threadIdx.x; i < FDIM * FDIM; i += blockDim.x) Ws[i] = W[i];
    __syncthreads();

    int r = blockIdx.x * blockDim.x + threadIdx.x;
    if (r >= n) return;

    unsigned long long acc2[FDIM / 2];
#pragma unroll
    for (int j = 0; j < FDIM / 2; j++) acc2[j] = 0ull;

    const float4* x4 = (const float4*)(in + (size_t)r * FDIM);
#pragma unroll 4
    for (int k4 = 0; k4 < FDIM / 4; k4++) {
        float4 xv = __ldg(x4 + k4);
        float xs[4] = {xv.x, xv.y, xv.z, xv.w};
#pragma unroll
        for (int kk = 0; kk < 4; kk++) {
            float xk = xs[kk];
            if (LRELU) xk = xk > 0.0f ? xk : 0.01f * xk;
            unsigned long long xk2 = pack2(xk);
            const ulonglong2* Wr = (const ulonglong2*)&Ws[(k4 * 4 + kk) * FDIM];
#pragma unroll
            for (int j = 0; j < FDIM / 4; j++) {
                ulonglong2 w2 = Wr[j];
                acc2[2 * j]     = ffma2(xk2, w2.x, acc2[2 * j]);
                acc2[2 * j + 1] = ffma2(xk2, w2.y, acc2[2 * j + 1]);
            }
        }
    }

    uint4* hr = (uint4*)(h + (size_t)r * FDIM);
#pragma unroll
    for (int j = 0; j < 8; j++) {
        float2 p0 = unpack2(acc2[4 * j + 0]);
        float2 p1 = unpack2(acc2[4 * j + 1]);
        float2 p2 = unpack2(acc2[4 * j + 2]);
        float2 p3 = unpack2(acc2[4 * j + 3]);
        uint4 v;
        v.x = h2_as_u32(__floats2half2_rn(p0.x, p0.y));
        v.y = h2_as_u32(__floats2half2_rn(p1.x, p1.y));
        v.z = h2_as_u32(__floats2half2_rn(p2.x, p2.y));
        v.w = h2_as_u32(__floats2half2_rn(p3.x, p3.y));
        hr[j] = v;
    }
}

// --- CSR gather: 16 lanes/node, lane owns 4 cols (uint2 = 4 halves = 8B).
//     Dual independent edge chains per thread: A=[0,m), B=[m,2m), m=deg/2.
__device__ __forceinline__ void acc_u2(uint2 u, float nn, float4& a) {
    __half2 h0 = *reinterpret_cast<__half2*>(&u.x);
    __half2 h1 = *reinterpret_cast<__half2*>(&u.y);
    float2 f0 = __half22float2(h0);
    float2 f1 = __half22float2(h1);
    a.x = fmaf(f0.x, nn, a.x); a.y = fmaf(f0.y, nn, a.y);
    a.z = fmaf(f1.x, nn, a.z); a.w = fmaf(f1.y, nn, a.w);
}

__global__ void __launch_bounds__(256)
k_gather(const __half* __restrict__ h, float* __restrict__ out,
         const float* __restrict__ b, int n) {
    int node = blockIdx.x * 16 + (threadIdx.x >> 4);
    if (node >= n) return;
    int l16 = threadIdx.x & 15;              // owns cols [4*l16, 4*l16+4)

    const uint2* h2 = (const uint2*)h;       // 16 uint2 per row
    int start = g_row[node];
    int deg   = g_cnt[node];
    float di  = g_dinv[node];
    float sn  = di * di;

    float4 a = __ldg((const float4*)b + l16);
    acc_u2(h2[(size_t)node * 16 + l16], sn, a);     // self loop + bias
    float4 a2 = make_float4(0.f, 0.f, 0.f, 0.f);    // chain-B accumulator

    const int2* ed = g_edata + start;
    int m = deg >> 1;                        // chain A=[0,m), B=[m,2m)
    int j = 0;
    for (; j + 2 <= m; j += 2) {             // 4 edges/iter, 8 loads in flight
        int2 ea0 = ed[j],     ea1 = ed[j + 1];
        int2 eb0 = ed[m + j], eb1 = ed[m + j + 1];
        uint2 va0 = h2[(size_t)ea0.x * 16 + l16];
        uint2 vb0 = h2[(size_t)eb0.x * 16 + l16];
        uint2 va1 = h2[(size_t)ea1.x * 16 + l16];
        uint2 vb1 = h2[(size_t)eb1.x * 16 + l16];
        acc_u2(va0, __int_as_float(ea0.y), a);
        acc_u2(vb0, __int_as_float(eb0.y), a2);
        acc_u2(va1, __int_as_float(ea1.y), a);
        acc_u2(vb1, __int_as_float(eb1.y), a2);
    }
    for (; j < m; j++) {
        int2 ea = ed[j], eb = ed[m + j];
        uint2 va = h2[(size_t)ea.x * 16 + l16];
        uint2 vb = h2[(size_t)eb.x * 16 + l16];
        acc_u2(va, __int_as_float(ea.y), a);
        acc_u2(vb, __int_as_float(eb.y), a2);
    }
    if (deg & 1) {                           // tail edge index 2m = deg-1
        int2 ee = ed[2 * m];
        uint2 v = h2[(size_t)ee.x * 16 + l16];
        acc_u2(v, __int_as_float(ee.y), a);
    }

    a.x += a2.x; a.y += a2.y; a.z += a2.z; a.w += a2.w;
    ((float4*)out)[(size_t)node * 16 + l16] = a;
}

extern "C" void kernel_launch(void* const* d_in, const int* in_sizes, int n_in,
                              void* d_out, int out_size) {
    const float* x  = (const float*)d_in[0];
    const void*  ei = d_in[1];
    const float* W1 = (const float*)d_in[2];
    const float* b1 = (const float*)d_in[3];
    const float* W2 = (const float*)d_in[4];
    const float* b2 = (const float*)d_in[5];
    const float* W3 = (const float*)d_in[6];
    const float* b3 = (const float*)d_in[7];
    float* out = (float*)d_out;

    int n = in_sizes[0] / FDIM;
    long long E = (long long)in_sizes[1] / 2;

    __half* hbuf;
    float* accbuf;
    cudaGetSymbolAddress((void**)&hbuf, g_h);
    cudaGetSymbolAddress((void**)&accbuf, g_acc);

    int nb_n  = (n + 255) / 256;
    int nb_e  = (int)((E + 255) / 256);
    int nb_g  = (n + 127) / 128;
    int nb_ga = (n + 15) / 16;

    k_prep0<<<nb_n, 256>>>((const unsigned int*)ei, 2 * E, n);  // 0
    k_deg<<<nb_e, 256>>>(ei, E);                                // 1
    k_dinv_alloc<<<nb_n, 256>>>(n);                             // 2
    k_fill<<<nb_e, 256>>>(ei, E);                               // 3 <- profiled
    k_gemm<0><<<nb_g, 128>>>(x, W1, hbuf, n);                   // 4
    k_gather<<<nb_ga, 256>>>(hbuf, accbuf, b1, n);              // 5
    k_gemm<1><<<nb_g, 128>>>(accbuf, W2, hbuf, n);              // 6
    k_gather<<<nb_ga, 256>>>(hbuf, accbuf, b2, n);              // 7
    k_gemm<1><<<nb_g, 128>>>(accbuf, W3, hbuf, n);              // 8
    k_gather<<<nb_ga, 256>>>(hbuf, out, b3, n);                 // 9
}